// round 2
// baseline (speedup 1.0000x reference)
#include <cuda_runtime.h>
#include <math.h>

#define DIM   192
#define NB    2
#define TW    32
#define TH    16
#define NT    (TW * TH)   // 512 threads
#define DC    48          // depth planes per block
#define SW    (TW + 2)    // 34
#define SH    (TH + 2)    // 18
#define PLANE (DIM * DIM)

__device__ double g_sum;

__global__ void zero_k() { g_sum = 0.0; }

__global__ void fin_k(float* out) {
    out[0] = (float)(g_sum / 14155776.0);   // 2*192^3
}

// Per-plane separable quantities at this thread's (h,w):
//   A = s_h(d_w(x)), B = d_h(s_w(x)), C = s_h(s_w(x)), V = center value
__device__ __forceinline__ void plane_q(const float* __restrict__ s, int lh, int lw,
                                        float& A, float& Bq, float& C, float& V)
{
    const float* r0 = s + (lh - 1) * SW + lw;
    const float* r1 = r0 + SW;
    const float* r2 = r1 + SW;
    float a0 = r0[-1], b0 = r0[0], c0 = r0[1];
    float a1 = r1[-1], b1 = r1[0], c1 = r1[1];
    float a2 = r2[-1], b2 = r2[0], c2 = r2[1];
    float sw0 = a0 + 2.f * b0 + c0, dw0 = c0 - a0;
    float sw1 = a1 + 2.f * b1 + c1, dw1 = c1 - a1;
    float sw2 = a2 + 2.f * b2 + c2, dw2 = c2 - a2;
    A  = dw0 + 2.f * dw1 + dw2;
    Bq = sw0 - sw2;
    C  = sw0 + 2.f * sw1 + sw2;
    V  = b1;
}

__device__ __forceinline__ void load_plane(const float* __restrict__ P,
                                           const float* __restrict__ G,
                                           float* __restrict__ dp,
                                           float* __restrict__ dg,
                                           int h0, int w0, int tid)
{
    for (int i = tid; i < SH * SW; i += NT) {
        int lhh = i / SW;
        int lww = i - lhh * SW;
        int gh = h0 - 1 + lhh;
        int gw = w0 - 1 + lww;
        float vp = 0.f, vg = 0.f;
        if ((unsigned)gh < DIM && (unsigned)gw < DIM) {
            int off = gh * DIM + gw;
            vp = P[off];
            vg = G[off];
        }
        dp[i] = vp;
        dg[i] = vg;
    }
}

__global__ __launch_bounds__(NT)
void loss_k(const float* __restrict__ pred,
            const float* __restrict__ gt,
            const float* __restrict__ mask)
{
    __shared__ float sp[2][SH * SW];
    __shared__ float sg[2][SH * SW];
    __shared__ float wred[NT / 32];

    const int tx = threadIdx.x, ty = threadIdx.y;
    const int tid = ty * 32 + tx;
    const int w0 = blockIdx.x * TW;
    const int h0 = blockIdx.y * TH;
    const int b  = blockIdx.z >> 2;          // DIM/DC = 4 chunks per batch
    const int d0 = (blockIdx.z & 3) * DC;
    const size_t base = (size_t)b * DIM * PLANE;

    const int lw = tx + 1, lh = ty + 1;

    // register rings: slot0 = plane d-1, slot1 = plane d, slot2 = plane d+1
    float pA0, pB0, pC0, pA1, pB1, pC1, pV1, pA2, pB2, pC2, pV2;
    float gA0, gB0, gC0, gA1, gB1, gC1, gV1, gA2, gB2, gC2, gV2;
    float dummy;

    // prologue: plane d0-1
    int pm = d0 - 1;
    if (pm >= 0) {
        load_plane(pred + base + (size_t)pm * PLANE, gt + base + (size_t)pm * PLANE,
                   sp[pm & 1], sg[pm & 1], h0, w0, tid);
        __syncthreads();
        plane_q(sp[pm & 1], lh, lw, pA0, pB0, pC0, dummy);
        plane_q(sg[pm & 1], lh, lw, gA0, gB0, gC0, dummy);
    } else {
        pA0 = pB0 = pC0 = 0.f;
        gA0 = gB0 = gC0 = 0.f;
    }
    // plane d0
    load_plane(pred + base + (size_t)d0 * PLANE, gt + base + (size_t)d0 * PLANE,
               sp[d0 & 1], sg[d0 & 1], h0, w0, tid);
    __syncthreads();
    plane_q(sp[d0 & 1], lh, lw, pA1, pB1, pC1, pV1);
    plane_q(sg[d0 & 1], lh, lw, gA1, gB1, gC1, gV1);

    float acc = 0.f;
    const float* mptr = mask + base + (size_t)(h0 + ty) * DIM + (w0 + tx);

    for (int d = d0; d < d0 + DC; ++d) {
        int dn = d + 1;
        if (dn < DIM) {
            load_plane(pred + base + (size_t)dn * PLANE, gt + base + (size_t)dn * PLANE,
                       sp[dn & 1], sg[dn & 1], h0, w0, tid);
            __syncthreads();
            plane_q(sp[dn & 1], lh, lw, pA2, pB2, pC2, pV2);
            plane_q(sg[dn & 1], lh, lw, gA2, gB2, gC2, gV2);
        } else {
            pA2 = pB2 = pC2 = pV2 = 0.f;
            gA2 = gB2 = gC2 = gV2 = 0.f;
        }

        // gradients at plane d (signs irrelevant to magnitude)
        float gxp = pA0 + 2.f * pA1 + pA2;
        float gyp = pB0 + 2.f * pB1 + pB2;
        float gzp = pC0 - pC2;
        float gxg = gA0 + 2.f * gA1 + gA2;
        float gyg = gB0 + 2.f * gB1 + gB2;
        float gzg = gC0 - gC2;

        float magp = sqrtf(gxp * gxp + gyp * gyp + gzp * gzp + 1e-10f);
        float magg = sqrtf(gxg * gxg + gyg * gyg + gzg * gzg + 1e-10f);

        float m    = mptr[(size_t)d * PLANE];
        float diff = pV1 - gV1;
        float mse  = diff * diff * m;
        float dmag = magg - magp;
        float mge  = dmag * dmag * m;
        acc += mse + tanhf(mge) * mse;

        // shift ring
        pA0 = pA1; pB0 = pB1; pC0 = pC1;
        pA1 = pA2; pB1 = pB2; pC1 = pC2; pV1 = pV2;
        gA0 = gA1; gB0 = gB1; gC0 = gC1;
        gA1 = gA2; gB1 = gB2; gC1 = gC2; gV1 = gV2;
    }

    // block reduction
    #pragma unroll
    for (int o = 16; o; o >>= 1)
        acc += __shfl_down_sync(0xffffffffu, acc, o);
    if (tx == 0) wred[ty] = acc;
    __syncthreads();
    if (tid == 0) {
        float s = 0.f;
        #pragma unroll
        for (int i = 0; i < NT / 32; i++) s += wred[i];
        atomicAdd(&g_sum, (double)s);
    }
}

extern "C" void kernel_launch(void* const* d_in, const int* in_sizes, int n_in,
                              void* d_out, int out_size)
{
    const float* pred = (const float*)d_in[0];
    const float* gt   = (const float*)d_in[1];
    const float* mask = (const float*)d_in[2];

    zero_k<<<1, 1>>>();
    dim3 grid(DIM / TW, DIM / TH, NB * (DIM / DC));   // 6 x 12 x 8 = 576 blocks
    dim3 blk(32, TH);
    loss_k<<<grid, blk>>>(pred, gt, mask);
    fin_k<<<1, 1>>>((float*)d_out);
}

// round 15
// speedup vs baseline: 1.6663x; 1.6663x over previous
#include <cuda_runtime.h>
#include <math.h>

#define DIM   192
#define NB    2
#define TW    32
#define TH    16
#define NT    (TW * TH)   // 512 threads
#define DC    48          // depth planes per block
#define SW    (TW + 2)    // 34
#define SH    (TH + 2)    // 18
#define SPL   (SH * SW)   // 612
#define PLANE (DIM * DIM)
#define GX    (DIM / TW)  // 6
#define GY    (DIM / TH)  // 12
#define GZ    (NB * (DIM / DC)) // 8
#define NBLK  (GX * GY * GZ)    // 576

__device__ float        g_part[NBLK];
__device__ unsigned int g_cnt;          // zero-initialized; self-resets each run

// Per-plane separable quantities at (lh,lw):
//   A = s_h(d_w(x)), B = d_h(s_w(x)), C = s_h(s_w(x)), V = center
__device__ __forceinline__ void plane_q(const float* __restrict__ s, int lh, int lw,
                                        float& A, float& Bq, float& C, float& V)
{
    const float* r0 = s + (lh - 1) * SW + lw;
    const float* r1 = r0 + SW;
    const float* r2 = r1 + SW;
    float a0 = r0[-1], b0 = r0[0], c0 = r0[1];
    float a1 = r1[-1], b1 = r1[0], c1 = r1[1];
    float a2 = r2[-1], b2 = r2[0], c2 = r2[1];
    float sw0 = a0 + 2.f * b0 + c0, dw0 = c0 - a0;
    float sw1 = a1 + 2.f * b1 + c1, dw1 = c1 - a1;
    float sw2 = a2 + 2.f * b2 + c2, dw2 = c2 - a2;
    A  = dw0 + 2.f * dw1 + dw2;
    Bq = sw0 - sw2;
    C  = sw0 + 2.f * sw1 + sw2;
    V  = b1;
}

// LDG one plane's worth of this thread's slots into registers (zeros when OOB)
__device__ __forceinline__ void ldg_plane(const float* __restrict__ P,
                                          const float* __restrict__ G,
                                          int d, int off0, int off1,
                                          bool ok0, bool ok1,
                                          float& p0, float& p1,
                                          float& g0, float& g1)
{
    p0 = p1 = g0 = g1 = 0.f;
    if ((unsigned)d < DIM) {
        const float* Pd = P + (size_t)d * PLANE;
        const float* Gd = G + (size_t)d * PLANE;
        if (ok0) { p0 = __ldg(Pd + off0); g0 = __ldg(Gd + off0); }
        if (ok1) { p1 = __ldg(Pd + off1); g1 = __ldg(Gd + off1); }
    }
}

__device__ __forceinline__ void sts_plane(float* __restrict__ dp,
                                          float* __restrict__ dg,
                                          int i0, int i1,
                                          float p0, float p1, float g0, float g1)
{
    dp[i0] = p0; dg[i0] = g0;
    if (i1 < SPL) { dp[i1] = p1; dg[i1] = g1; }
}

__global__ __launch_bounds__(NT)
void loss_k(const float* __restrict__ pred,
            const float* __restrict__ gt,
            const float* __restrict__ mask,
            float* __restrict__ out)
{
    __shared__ float sp[2][SPL];
    __shared__ float sg[2][SPL];
    __shared__ float wred[NT / 32];
    __shared__ bool  isLast;

    const int tx = threadIdx.x, ty = threadIdx.y;
    const int tid = ty * 32 + tx;
    const int w0 = blockIdx.x * TW;
    const int h0 = blockIdx.y * TH;
    const int b  = blockIdx.z >> 2;          // DIM/DC = 4 chunks per batch
    const int d0 = (blockIdx.z & 3) * DC;
    const size_t base = (size_t)b * DIM * PLANE;
    const float* P = pred + base;
    const float* G = gt   + base;

    // thread's two halo-load slots (same (h,w) geometry every plane)
    const int i0 = tid, i1 = tid + NT;
    int  lh0 = i0 / SW, lw0 = i0 - lh0 * SW;
    int  gh0 = h0 - 1 + lh0, gw0 = w0 - 1 + lw0;
    bool ok0 = (unsigned)gh0 < DIM && (unsigned)gw0 < DIM;
    int  off0 = gh0 * DIM + gw0;
    int  lh1 = i1 / SW, lw1 = i1 - lh1 * SW;
    int  gh1 = h0 - 1 + lh1, gw1 = w0 - 1 + lw1;
    bool ok1 = (i1 < SPL) && (unsigned)gh1 < DIM && (unsigned)gw1 < DIM;
    int  off1 = gh1 * DIM + gw1;

    const int lw = tx + 1, lh = ty + 1;

    // register rings
    float pA0, pB0, pC0, pA1, pB1, pC1, pV1, pA2, pB2, pC2, pV2;
    float gA0, gB0, gC0, gA1, gB1, gC1, gV1, gA2, gB2, gC2, gV2;
    float dummy;

    // ---- prologue: planes d0-1 and d0 straight into the two buffers ----
    {
        float a, bb, c, dd;
        ldg_plane(P, G, d0 - 1, off0, off1, ok0, ok1, a, bb, c, dd);
        sts_plane(sp[1], sg[1], i0, i1, a, bb, c, dd);   // (d0-1)&1 == 1 (d0 even)
        ldg_plane(P, G, d0, off0, off1, ok0, ok1, a, bb, c, dd);
        sts_plane(sp[0], sg[0], i0, i1, a, bb, c, dd);
        __syncthreads();
        plane_q(sp[1], lh, lw, pA0, pB0, pC0, dummy);
        plane_q(sg[1], lh, lw, gA0, gB0, gC0, dummy);
        plane_q(sp[0], lh, lw, pA1, pB1, pC1, pV1);
        plane_q(sg[0], lh, lw, gA1, gB1, gC1, gV1);
        __syncthreads();   // both buffers still live until everyone is done reading
    }

    // prefetch plane d0+1 into registers, and mask for d0
    float rp0, rp1, rg0, rg1;
    ldg_plane(P, G, d0 + 1, off0, off1, ok0, ok1, rp0, rp1, rg0, rg1);
    const float* mptr = mask + base + (size_t)(h0 + ty) * DIM + (w0 + tx);
    float mcur = mptr[(size_t)d0 * PLANE];

    float acc = 0.f;

    #pragma unroll 2
    for (int d = d0; d < d0 + DC; ++d) {
        const int dn = d + 1;
        const int bn = dn & 1;

        // stage prefetched plane dn into smem (regs loaded ~1 iter ago)
        sts_plane(sp[bn], sg[bn], i0, i1, rp0, rp1, rg0, rg1);
        __syncthreads();

        // issue LDG for plane d+2 (consumed next iteration) + next mask
        ldg_plane(P, G, d + 2, off0, off1, ok0, ok1, rp0, rp1, rg0, rg1);
        float mnext = (dn < d0 + DC) ? mptr[(size_t)dn * PLANE] : 0.f;

        // plane quantities for dn
        plane_q(sp[bn], lh, lw, pA2, pB2, pC2, pV2);
        plane_q(sg[bn], lh, lw, gA2, gB2, gC2, gV2);

        // gradients at plane d (signs irrelevant to magnitude)
        float gxp = pA0 + 2.f * pA1 + pA2;
        float gyp = pB0 + 2.f * pB1 + pB2;
        float gzp = pC0 - pC2;
        float gxg = gA0 + 2.f * gA1 + gA2;
        float gyg = gB0 + 2.f * gB1 + gB2;
        float gzg = gC0 - gC2;

        float magp = sqrtf(gxp * gxp + gyp * gyp + gzp * gzp + 1e-10f);
        float magg = sqrtf(gxg * gxg + gyg * gyg + gzg * gzg + 1e-10f);

        float diff = pV1 - gV1;
        float mse  = diff * diff * mcur;
        float dmag = magg - magp;
        float mge  = dmag * dmag * mcur;
        acc += mse + tanhf(mge) * mse;
        mcur = mnext;

        // shift rings
        pA0 = pA1; pB0 = pB1; pC0 = pC1;
        pA1 = pA2; pB1 = pB2; pC1 = pC2; pV1 = pV2;
        gA0 = gA1; gB0 = gB1; gC0 = gC1;
        gA1 = gA2; gB1 = gB2; gC1 = gC2; gV1 = gV2;
    }

    // block reduction (float partial)
    #pragma unroll
    for (int o = 16; o; o >>= 1)
        acc += __shfl_down_sync(0xffffffffu, acc, o);
    if (tx == 0) wred[ty] = acc;
    __syncthreads();

    const int bid = (blockIdx.z * GY + blockIdx.y) * GX + blockIdx.x;
    if (tid == 0) {
        float s = 0.f;
        #pragma unroll
        for (int i = 0; i < NT / 32; i++) s += wred[i];
        g_part[bid] = s;
        __threadfence();
        unsigned t = atomicAdd(&g_cnt, 1u);
        isLast = (t == NBLK - 1);
    }
    __syncthreads();

    // last block finalizes (and resets the ticket for the next graph replay)
    if (isLast) {
        __threadfence();
        const volatile float* vp = g_part;
        double local = 0.0;
        for (int i = tid; i < NBLK; i += NT) local += (double)vp[i];
        #pragma unroll
        for (int o = 16; o; o >>= 1)
            local += __shfl_down_sync(0xffffffffu, local, o);
        __shared__ double dred[NT / 32];
        if (tx == 0) dred[ty] = local;
        __syncthreads();
        if (tid == 0) {
            double s = 0.0;
            #pragma unroll
            for (int i = 0; i < NT / 32; i++) s += dred[i];
            out[0] = (float)(s / 14155776.0);   // 2*192^3
            g_cnt = 0;
        }
    }
}

extern "C" void kernel_launch(void* const* d_in, const int* in_sizes, int n_in,
                              void* d_out, int out_size)
{
    const float* pred = (const float*)d_in[0];
    const float* gt   = (const float*)d_in[1];
    const float* mask = (const float*)d_in[2];

    dim3 grid(GX, GY, GZ);   // 6 x 12 x 8 = 576 blocks
    dim3 blk(32, TH);
    loss_k<<<grid, blk>>>(pred, gt, mask, (float*)d_out);
}